// round 11
// baseline (speedup 1.0000x reference)
#include <cuda_runtime.h>
#include <cstdint>

#define BB 256
#define LL 512
#define DD 64
#define NSPLIT 2
#define NBLK (BB * NSPLIT)        // 512 blocks
#define EPS_LOG 1e-7f
#define EPS_COS 1e-8f

__device__ float g_m[NBLK];
__device__ float g_pos[NBLK];
__device__ float g_neg[NBLK];
__device__ int   g_cnt = 0;

__global__ __launch_bounds__(256)
void wnl_fused(const float* __restrict__ emb,
               const float* __restrict__ probs,
               const float* __restrict__ labels,
               float* __restrict__ out)
{
    const int bid  = blockIdx.x;       // 0..511
    const int b    = bid >> 1;         // batch 0..255
    const int h    = bid & 1;          // half 0/1
    const int tid  = threadIdx.x;      // 0..255
    const int wid  = tid >> 5;         // 0..7
    const int lane = tid & 31;
    const int g    = lane >> 3;        // 4 row-groups per warp
    const int s    = lane & 7;         // 8 lanes per row

    __shared__ float s_m[8], s_pos[8], s_neg[8], s_sum[8];
    __shared__ int   s_last;

    const float* __restrict__ embB = emb    + (size_t)b * LL * DD;
    const float* __restrict__ labB = labels + (size_t)b * LL;
    const float* __restrict__ prbB = probs  + (size_t)b * LL;

    if (tid == 0) s_last = 0;

    // labels[b][b] != 0  =>  weak-negative weight is 0 => skip all cosine work
    const float labdiag = __ldg(&labB[b]);

    float m = 0.f;
    if (labdiag == 0.f) {
        const int rowBase = h * 256 + wid * 32;     // warp covers 32 rows

        // all 32 row-labels for this warp in one coalesced load
        const float lv = labB[rowBase + lane];

        // ---- PHASE 1: issue ALL predicated row loads (no consumers yet) ----
        // ~16 independent LDG.128 in flight per warp -> DRAM latency paid once
        float4 xa[8], xb[8];
        float  labv[8];
        #pragma unroll
        for (int it = 0; it < 8; it++) {
            const float lab = __shfl_sync(0xffffffffu, lv, it * 4 + g);
            labv[it] = lab;
            xa[it] = make_float4(0.f, 0.f, 0.f, 0.f);
            xb[it] = make_float4(0.f, 0.f, 0.f, 0.f);
            if (lab != 0.f) {                       // label==0 rows contribute 0
                const float* rp = embB + (size_t)(rowBase + it * 4 + g) * DD;
                xa[it] = *(const float4*)(rp + s * 4);
                xb[it] = *(const float4*)(rp + 32 + s * 4);
            }
        }

        // query row per lane (L1-resident after first warp touches it)
        const float4 qa = *(const float4*)(embB + (size_t)b * DD + s * 4);
        const float4 qb = *(const float4*)(embB + (size_t)b * DD + 32 + s * 4);
        float nq2 = qa.x*qa.x + qa.y*qa.y + qa.z*qa.z + qa.w*qa.w
                  + qb.x*qb.x + qb.y*qb.y + qb.z*qb.z + qb.w*qb.w;
        #pragma unroll
        for (int o = 4; o; o >>= 1) nq2 += __shfl_xor_sync(0xffffffffu, nq2, o);
        const float nq = sqrtf(nq2);

        // ---- PHASE 2: reduce (loads already in flight / arrived) ----
        #pragma unroll
        for (int it = 0; it < 8; it++) {
            const float4 va = xa[it], vb = xb[it];
            float d = qa.x*va.x + qa.y*va.y + qa.z*va.z + qa.w*va.w
                    + qb.x*vb.x + qb.y*vb.y + qb.z*vb.z + qb.w*vb.w;
            float n = va.x*va.x + va.y*va.y + va.z*va.z + va.w*va.w
                    + vb.x*vb.x + vb.y*vb.y + vb.z*vb.z + vb.w*vb.w;
            #pragma unroll
            for (int o = 4; o; o >>= 1) {
                d += __shfl_xor_sync(0xffffffffu, d, o);
                n += __shfl_xor_sync(0xffffffffu, n, o);
            }
            const float cosv = d / fmaxf(nq * sqrtf(n), EPS_COS);
            m = fmaxf(m, fmaxf(cosv, 0.f) * labv[it]);
        }
    }

    // ---- this half's log sums (one l per thread; pos term always needed) ----
    const int   l  = h * 256 + tid;
    const float pe = prbB[l] + EPS_LOG;
    float pos = labB[l] * logf(pe);
    float neg = logf(1.0f - pe);

    // warp combine: max(m), sum(pos), sum(neg)
    #pragma unroll
    for (int o = 16; o; o >>= 1) {
        m    = fmaxf(m, __shfl_xor_sync(0xffffffffu, m, o));
        pos += __shfl_xor_sync(0xffffffffu, pos, o);
        neg += __shfl_xor_sync(0xffffffffu, neg, o);
    }
    if (lane == 0) { s_m[wid] = m; s_pos[wid] = pos; s_neg[wid] = neg; }
    __syncthreads();

    if (wid == 0) {
        float mm = (lane < 8) ? s_m[lane]   : 0.f;
        float pp = (lane < 8) ? s_pos[lane] : 0.f;
        float nn = (lane < 8) ? s_neg[lane] : 0.f;
        #pragma unroll
        for (int o = 4; o; o >>= 1) {
            mm = fmaxf(mm, __shfl_xor_sync(0xffffffffu, mm, o));
            pp += __shfl_xor_sync(0xffffffffu, pp, o);
            nn += __shfl_xor_sync(0xffffffffu, nn, o);
        }
        if (lane == 0) {
            g_m[bid] = mm; g_pos[bid] = pp; g_neg[bid] = nn;
            __threadfence();
            const int old = atomicAdd(&g_cnt, 1);
            if (old == NBLK - 1) s_last = 1;   // this block finishes the job
        }
    }
    __syncthreads();

    // ---- last-block final combine (deterministic fixed-order sum) ----
    if (s_last) {
        __threadfence();
        const int b2 = tid;                    // one batch per thread
        float mm = fmaxf(__ldcg(&g_m[2*b2]),  __ldcg(&g_m[2*b2+1]));
        float pp = __ldcg(&g_pos[2*b2]) + __ldcg(&g_pos[2*b2+1]);
        float nn = __ldcg(&g_neg[2*b2]) + __ldcg(&g_neg[2*b2+1]);
        const float ld2 = __ldg(&labels[(size_t)b2 * LL + b2]);
        const float wnl = (ld2 == 0.f) ? mm : 0.f;
        float contrib = -pp - wnl * nn;

        #pragma unroll
        for (int o = 16; o; o >>= 1)
            contrib += __shfl_xor_sync(0xffffffffu, contrib, o);
        if (lane == 0) s_sum[wid] = contrib;
        __syncthreads();
        if (wid == 0) {
            float t = (lane < 8) ? s_sum[lane] : 0.f;
            #pragma unroll
            for (int o = 4; o; o >>= 1) t += __shfl_xor_sync(0xffffffffu, t, o);
            if (lane == 0) {
                out[0] = t / (float)BB;
                g_cnt = 0;                     // reset for next graph replay
            }
        }
    }
}

extern "C" void kernel_launch(void* const* d_in, const int* in_sizes, int n_in,
                              void* d_out, int out_size)
{
    const float* emb    = (const float*)d_in[0]; // (256, 512, 64) f32
    const float* probs  = (const float*)d_in[1]; // (256, 512) f32
    const float* labels = (const float*)d_in[2]; // (256, 512) f32
    float* out = (float*)d_out;                  // scalar f32

    wnl_fused<<<NBLK, 256>>>(emb, probs, labels, out);
}

// round 12
// speedup vs baseline: 1.0536x; 1.0536x over previous
#include <cuda_runtime.h>
#include <cstdint>

#define BB 256
#define LL 512
#define DD 64
#define NSPLIT 4
#define NBLK (BB * NSPLIT)        // 1024 blocks
#define RPB 128                   // rows per block (quarter batch)
#define RPW 16                    // rows per warp
#define EPS_LOG 1e-7f
#define EPS_COS 1e-8f

__device__ float g_m[NBLK];
__device__ float g_pos[NBLK];
__device__ float g_neg[NBLK];
__device__ int   g_cnt = 0;

__device__ __forceinline__ void cp_async16(unsigned int dst, const void* src) {
    asm volatile("cp.async.cg.shared.global [%0], [%1], 16;" :: "r"(dst), "l"(src));
}

__global__ __launch_bounds__(256)
void wnl_fused(const float* __restrict__ emb,
               const float* __restrict__ probs,
               const float* __restrict__ labels,
               float* __restrict__ out)
{
    const int bid  = blockIdx.x;       // 0..1023
    const int b    = bid >> 2;         // batch 0..255
    const int qtr  = bid & 3;          // quarter 0..3
    const int tid  = threadIdx.x;      // 0..255
    const int wid  = tid >> 5;         // 0..7
    const int lane = tid & 31;
    const int g    = lane >> 3;        // 4 row-groups per warp
    const int s    = lane & 7;         // 8 lanes per row

    // per-warp strip: 16 rows x 16 float4 chunks, XOR-swizzled (j^r)
    __shared__ float4 tile[8 * RPW * 16];          // 32 KB
    __shared__ float  s_m[8], s_pos[8], s_neg[8], s_sum[8];
    __shared__ int    s_last;

    const float* __restrict__ embB = emb    + (size_t)b * LL * DD;
    const float* __restrict__ labB = labels + (size_t)b * LL;
    const float* __restrict__ prbB = probs  + (size_t)b * LL;

    if (tid == 0) s_last = 0;

    // labels[b][b] != 0  =>  weak-negative weight 0 => no cosine work at all
    const float labdiag = __ldg(&labB[b]);
    const bool  live    = (labdiag == 0.f);

    const int rowBase = qtr * RPB + wid * RPW;     // warp covers 16 rows
    float lv = 0.f;                                // this warp's 16 row labels
    float4 qa, qb;
    float  nq = 0.f;

    if (live) {
        lv = labB[rowBase + (lane & 15)];

        // ---- predicated cp.async: no dest regs -> all live chunks in flight ----
        float4* strip = &tile[wid * (RPW * 16)];
        const char* src0 = (const char*)(embB + (size_t)rowBase * DD);
        #pragma unroll
        for (int c = 0; c < 8; c++) {
            const int id = lane + c * 32;          // chunk id 0..255
            const int r  = id >> 4;                // row 0..15
            const int j  = id & 15;                // chunk within row
            const float lab = __shfl_sync(0xffffffffu, lv, r);
            if (lab != 0.f) {                      // dead rows: never loaded/read
                unsigned int dst = (unsigned int)__cvta_generic_to_shared(
                                       &strip[r * 16 + (j ^ r)]);
                cp_async16(dst, src0 + (size_t)id * 16);
            }
        }
        asm volatile("cp.async.commit_group;");

        // query row per lane (independent load, overlaps with cp.async)
        qa = *(const float4*)(embB + (size_t)b * DD + s * 4);
        qb = *(const float4*)(embB + (size_t)b * DD + 32 + s * 4);
        float nq2 = qa.x*qa.x + qa.y*qa.y + qa.z*qa.z + qa.w*qa.w
                  + qb.x*qb.x + qb.y*qb.y + qb.z*qb.z + qb.w*qb.w;
        #pragma unroll
        for (int o = 4; o; o >>= 1) nq2 += __shfl_xor_sync(0xffffffffu, nq2, o);
        nq = sqrtf(nq2);
    }

    // ---- logs overlap the async loads (MUFU under DRAM latency) ----
    float pos = 0.f, neg = 0.f;
    if (tid < RPB) {
        const int l = qtr * RPB + tid;
        const float pe = prbB[l] + EPS_LOG;
        pos = labB[l] * logf(pe);
        neg = logf(1.0f - pe);
    }

    asm volatile("cp.async.wait_group 0;");
    __syncthreads();                               // cross-lane smem visibility

    // ---- cosine from smem: 4 iterations x 4 rows, 8 lanes/row ----
    float m = 0.f;
    if (live) {
        const float4* strip = &tile[wid * (RPW * 16)];
        #pragma unroll
        for (int it = 0; it < 4; it++) {
            const int r = it * 4 + g;
            const float lab = __shfl_sync(0xffffffffu, lv, r);
            float4 xa = make_float4(0.f, 0.f, 0.f, 0.f);
            float4 xb = make_float4(0.f, 0.f, 0.f, 0.f);
            if (lab != 0.f) {                      // zeros -> exact 0 contribution
                xa = strip[r * 16 + (s ^ r)];
                xb = strip[r * 16 + ((8 + s) ^ r)];
            }
            float d = qa.x*xa.x + qa.y*xa.y + qa.z*xa.z + qa.w*xa.w
                    + qb.x*xb.x + qb.y*xb.y + qb.z*xb.z + qb.w*xb.w;
            float n = xa.x*xa.x + xa.y*xa.y + xa.z*xa.z + xa.w*xa.w
                    + xb.x*xb.x + xb.y*xb.y + xb.z*xb.z + xb.w*xb.w;
            #pragma unroll
            for (int o = 4; o; o >>= 1) {
                d += __shfl_xor_sync(0xffffffffu, d, o);
                n += __shfl_xor_sync(0xffffffffu, n, o);
            }
            const float cosv = d / fmaxf(nq * sqrtf(n), EPS_COS);
            m = fmaxf(m, fmaxf(cosv, 0.f) * lab);
        }
    }

    // ---- warp combine: max(m), sum(pos), sum(neg) ----
    #pragma unroll
    for (int o = 16; o; o >>= 1) {
        m    = fmaxf(m, __shfl_xor_sync(0xffffffffu, m, o));
        pos += __shfl_xor_sync(0xffffffffu, pos, o);
        neg += __shfl_xor_sync(0xffffffffu, neg, o);
    }
    if (lane == 0) { s_m[wid] = m; s_pos[wid] = pos; s_neg[wid] = neg; }
    __syncthreads();

    if (wid == 0) {
        float mm = (lane < 8) ? s_m[lane]   : 0.f;
        float pp = (lane < 8) ? s_pos[lane] : 0.f;
        float nn = (lane < 8) ? s_neg[lane] : 0.f;
        #pragma unroll
        for (int o = 4; o; o >>= 1) {
            mm = fmaxf(mm, __shfl_xor_sync(0xffffffffu, mm, o));
            pp += __shfl_xor_sync(0xffffffffu, pp, o);
            nn += __shfl_xor_sync(0xffffffffu, nn, o);
        }
        if (lane == 0) {
            g_m[bid] = mm; g_pos[bid] = pp; g_neg[bid] = nn;
            __threadfence();
            const int old = atomicAdd(&g_cnt, 1);
            if (old == NBLK - 1) s_last = 1;   // this block finishes the job
        }
    }
    __syncthreads();

    // ---- last-block final combine (deterministic fixed-order sum) ----
    if (s_last) {
        __threadfence();
        const int b2 = tid;                    // one batch per thread
        float mm = __ldcg(&g_m[4*b2]);
        float pp = __ldcg(&g_pos[4*b2]);
        float nn = __ldcg(&g_neg[4*b2]);
        #pragma unroll
        for (int j = 1; j < NSPLIT; j++) {
            mm = fmaxf(mm, __ldcg(&g_m[4*b2 + j]));
            pp += __ldcg(&g_pos[4*b2 + j]);
            nn += __ldcg(&g_neg[4*b2 + j]);
        }
        const float ld2 = __ldg(&labels[(size_t)b2 * LL + b2]);
        const float wnl = (ld2 == 0.f) ? mm : 0.f;
        float contrib = -pp - wnl * nn;

        #pragma unroll
        for (int o = 16; o; o >>= 1)
            contrib += __shfl_xor_sync(0xffffffffu, contrib, o);
        if (lane == 0) s_sum[wid] = contrib;
        __syncthreads();
        if (wid == 0) {
            float t = (lane < 8) ? s_sum[lane] : 0.f;
            #pragma unroll
            for (int o = 4; o; o >>= 1) t += __shfl_xor_sync(0xffffffffu, t, o);
            if (lane == 0) {
                out[0] = t / (float)BB;
                g_cnt = 0;                     // reset for next graph replay
            }
        }
    }
}

extern "C" void kernel_launch(void* const* d_in, const int* in_sizes, int n_in,
                              void* d_out, int out_size)
{
    const float* emb    = (const float*)d_in[0]; // (256, 512, 64) f32
    const float* probs  = (const float*)d_in[1]; // (256, 512) f32
    const float* labels = (const float*)d_in[2]; // (256, 512) f32
    float* out = (float*)d_out;                  // scalar f32

    wnl_fused<<<NBLK, 256>>>(emb, probs, labels, out);
}

// round 14
// speedup vs baseline: 1.4568x; 1.3827x over previous
#include <cuda_runtime.h>
#include <cstdint>

#define BB 256
#define LL 512
#define DD 64
#define NSPLIT 2
#define NBLK (BB * NSPLIT)        // 512 blocks
#define EPS_LOG 1e-7f
#define EPS_COS 1e-8f

__device__ float g_m[NBLK];
__device__ float g_pos[NBLK];
__device__ float g_neg[NBLK];
__device__ int   g_cnt = 0;

__global__ __launch_bounds__(256)
void wnl_fused(const float* __restrict__ emb,
               const float* __restrict__ probs,
               const float* __restrict__ labels,
               float* __restrict__ out)
{
    const int bid  = blockIdx.x;       // 0..511
    const int b    = bid >> 1;         // batch 0..255
    const int h    = bid & 1;          // half 0/1
    const int tid  = threadIdx.x;      // 0..255
    const int wid  = tid >> 5;         // 0..7
    const int lane = tid & 31;
    const int g    = lane >> 3;        // 4 row-groups per warp
    const int s    = lane & 7;         // 8 lanes per row

    __shared__ float s_m[8], s_pos[8], s_neg[8], s_sum[8];
    __shared__ int   s_last;

    const float* __restrict__ embB = emb    + (size_t)b * LL * DD;
    const float* __restrict__ labB = labels + (size_t)b * LL;
    const float* __restrict__ prbB = probs  + (size_t)b * LL;

    if (tid == 0) s_last = 0;

    const int rowBase = h * 256 + wid * 32;    // warp covers 32 rows

    // ---- issue ALL control loads at cycle 0 (independent of each other) ----
    const float labdiag = __ldg(&labB[b]);               // gate for whole batch
    const float lv      = labB[rowBase + lane];          // 32 row labels / warp
    const float pr      = prbB[h * 256 + tid];           // prob for log terms
    const float myl     = labB[h * 256 + tid];           // label for pos term
    // query row per lane (tiny: 256B/block; always load, no dependency)
    const float4 qa = *(const float4*)(embB + (size_t)b * DD + s * 4);
    const float4 qb = *(const float4*)(embB + (size_t)b * DD + 32 + s * 4);

    float m = 0.f;
    if (labdiag == 0.f) {                      // dead batches skip all emb reads
        float nq2 = qa.x*qa.x + qa.y*qa.y + qa.z*qa.z + qa.w*qa.w
                  + qb.x*qb.x + qb.y*qb.y + qb.z*qb.z + qb.w*qb.w;
        #pragma unroll
        for (int o = 4; o; o >>= 1) nq2 += __shfl_xor_sync(0xffffffffu, nq2, o);
        const float nq = sqrtf(nq2);

        #pragma unroll
        for (int it = 0; it < 8; it++) {
            const int   k   = rowBase + it * 4 + g;
            const float lab = __shfl_sync(0xffffffffu, lv, it * 4 + g);
            // BRANCHLESS predicated load: dead rows read the (L1-resident)
            // query row instead -> no BSSY region, loads batch freely,
            // ~zero extra DRAM. Result is erased exactly by *lab below.
            const size_t roff = (lab != 0.f) ? (size_t)k * DD : (size_t)b * DD;
            const float* rp = embB + roff;
            const float4 xa = *(const float4*)(rp + s * 4);
            const float4 xb = *(const float4*)(rp + 32 + s * 4);
            float d = qa.x*xa.x + qa.y*xa.y + qa.z*xa.z + qa.w*xa.w
                    + qb.x*xb.x + qb.y*xb.y + qb.z*xb.z + qb.w*xb.w;
            float n = xa.x*xa.x + xa.y*xa.y + xa.z*xa.z + xa.w*xa.w
                    + xb.x*xb.x + xb.y*xb.y + xb.z*xb.z + xb.w*xb.w;
            #pragma unroll
            for (int o = 4; o; o >>= 1) {
                d += __shfl_xor_sync(0xffffffffu, d, o);
                n += __shfl_xor_sync(0xffffffffu, n, o);
            }
            const float cosv = __fdividef(d, fmaxf(nq * sqrtf(n), EPS_COS));
            m = fmaxf(m, fmaxf(cosv, 0.f) * lab);   // lab==0 -> exact 0
        }
    }

    // ---- log terms (fast-math logs; err ~1e-6 << 1e-3 tolerance) ----
    const float pe  = pr + EPS_LOG;
    float pos = myl * __logf(pe);
    float neg = __logf(1.0f - pe);

    // ---- warp combine: max(m), sum(pos), sum(neg) ----
    #pragma unroll
    for (int o = 16; o; o >>= 1) {
        m    = fmaxf(m, __shfl_xor_sync(0xffffffffu, m, o));
        pos += __shfl_xor_sync(0xffffffffu, pos, o);
        neg += __shfl_xor_sync(0xffffffffu, neg, o);
    }
    if (lane == 0) { s_m[wid] = m; s_pos[wid] = pos; s_neg[wid] = neg; }
    __syncthreads();

    if (wid == 0) {
        float mm = (lane < 8) ? s_m[lane]   : 0.f;
        float pp = (lane < 8) ? s_pos[lane] : 0.f;
        float nn = (lane < 8) ? s_neg[lane] : 0.f;
        #pragma unroll
        for (int o = 4; o; o >>= 1) {
            mm = fmaxf(mm, __shfl_xor_sync(0xffffffffu, mm, o));
            pp += __shfl_xor_sync(0xffffffffu, pp, o);
            nn += __shfl_xor_sync(0xffffffffu, nn, o);
        }
        if (lane == 0) {
            g_m[bid] = mm; g_pos[bid] = pp; g_neg[bid] = nn;
            __threadfence();
            const int old = atomicAdd(&g_cnt, 1);
            if (old == NBLK - 1) s_last = 1;   // this block finishes the job
        }
    }
    __syncthreads();

    // ---- last-block final combine (deterministic fixed-order) ----
    if (s_last) {
        __threadfence();
        const int b2 = tid;                    // one batch per thread
        float mm = fmaxf(__ldcg(&g_m[2*b2]),  __ldcg(&g_m[2*b2+1]));
        float pp = __ldcg(&g_pos[2*b2]) + __ldcg(&g_pos[2*b2+1]);
        float nn = __ldcg(&g_neg[2*b2]) + __ldcg(&g_neg[2*b2+1]);
        const float ld2 = __ldg(&labels[(size_t)b2 * LL + b2]);
        const float wnl = (ld2 == 0.f) ? mm : 0.f;
        float contrib = -pp - wnl * nn;

        #pragma unroll
        for (int o = 16; o; o >>= 1)
            contrib += __shfl_xor_sync(0xffffffffu, contrib, o);
        if (lane == 0) s_sum[wid] = contrib;
        __syncthreads();
        if (wid == 0) {
            float t = (lane < 8) ? s_sum[lane] : 0.f;
            #pragma unroll
            for (int o = 4; o; o >>= 1) t += __shfl_xor_sync(0xffffffffu, t, o);
            if (lane == 0) {
                out[0] = t / (float)BB;
                g_cnt = 0;                     // reset for next graph replay
            }
        }
    }
}

extern "C" void kernel_launch(void* const* d_in, const int* in_sizes, int n_in,
                              void* d_out, int out_size)
{
    const float* emb    = (const float*)d_in[0]; // (256, 512, 64) f32
    const float* probs  = (const float*)d_in[1]; // (256, 512) f32
    const float* labels = (const float*)d_in[2]; // (256, 512) f32
    float* out = (float*)d_out;                  // scalar f32

    wnl_fused<<<NBLK, 256>>>(emb, probs, labels, out);
}